// round 7
// baseline (speedup 1.0000x reference)
#include <cuda_runtime.h>
#include <cuda_bf16.h>
#include <cstdint>

#define B_   8
#define C_   256
#define N_   4096
#define M_   1024
#define HD_  64
#define EPSV 1e-5f

// fp8 scale factors
#define SQ_  16.0f
#define SK_  8.0f
#define SV_  8.0f

// ===================== helpers =====================
__device__ __forceinline__ uint32_t smem_u32(const void* p) {
    uint32_t a;
    asm("{ .reg .u64 tmp; cvta.to.shared.u64 tmp, %1; cvt.u32.u64 %0, tmp; }" : "=r"(a) : "l"(p));
    return a;
}
__device__ __forceinline__ void ldmx4(uint32_t r[4], uint32_t addr) {
    asm volatile("ldmatrix.sync.aligned.m8n8.x4.shared.b16 {%0,%1,%2,%3}, [%4];"
                 : "=r"(r[0]), "=r"(r[1]), "=r"(r[2]), "=r"(r[3]) : "r"(addr));
}
__device__ __forceinline__ void mma16816(float c[4], const uint32_t a[4], uint32_t b0, uint32_t b1) {
    asm volatile("mma.sync.aligned.m16n8k16.row.col.f32.bf16.bf16.f32 "
                 "{%0,%1,%2,%3}, {%4,%5,%6,%7}, {%8,%9}, {%0,%1,%2,%3};"
                 : "+f"(c[0]), "+f"(c[1]), "+f"(c[2]), "+f"(c[3])
                 : "r"(a[0]), "r"(a[1]), "r"(a[2]), "r"(a[3]), "r"(b0), "r"(b1));
}
__device__ __forceinline__ void mma16832_e4m3(float c[4], const uint32_t a[4], uint32_t b0, uint32_t b1) {
    asm volatile("mma.sync.aligned.m16n8k32.row.col.f32.e4m3.e4m3.f32 "
                 "{%0,%1,%2,%3}, {%4,%5,%6,%7}, {%8,%9}, {%0,%1,%2,%3};"
                 : "+f"(c[0]), "+f"(c[1]), "+f"(c[2]), "+f"(c[3])
                 : "r"(a[0]), "r"(a[1]), "r"(a[2]), "r"(a[3]), "r"(b0), "r"(b1));
}
__device__ __forceinline__ float ex2f(float x) {
    float r; asm("ex2.approx.ftz.f32 %0, %1;" : "=f"(r) : "f"(x)); return r;
}
__device__ __forceinline__ uint32_t pack_bf16x2(float lo, float hi) {
    uint32_t r;
    asm("cvt.rn.satfinite.bf16x2.f32 %0, %1, %2;" : "=r"(r) : "f"(hi), "f"(lo));
    return r;
}
__device__ __forceinline__ uint16_t pack_e4m3x2(float lo, float hi) {
    uint16_t r;
    asm("cvt.rn.satfinite.e4m3x2.f32 %0, %1, %2;" : "=h"(r) : "f"(hi), "f"(lo));
    return r;
}
__device__ __forceinline__ uint32_t pack_e4m3x4(float v0, float v1, float v2, float v3) {
    uint16_t lo = pack_e4m3x2(v0, v1), hi = pack_e4m3x2(v2, v3);
    return (uint32_t)lo | ((uint32_t)hi << 16);
}
// V m-permutation (16-periodic): k-index <-> m so S frags pack directly into PV A-frags
__device__ __forceinline__ int perm_v(int r) {
    return (r & ~15) | (((r >> 1) & 3) << 2) | (((r >> 3) & 1) << 1) | (r & 1);
}

// ===================== device scratch =====================
__device__ float g_part[B_ * 64 * 2];
__device__ float g_s[B_ * C_];
__device__ float g_t[B_ * C_];
__device__ __nv_bfloat16 g_xt [(size_t)B_ * N_ * C_];   // normalized, [b][n][c]
__device__ __nv_bfloat16 g_xds[(size_t)B_ * M_ * C_];   // pooled+norm, [b][m][c]
__device__ __nv_bfloat16 g_wqb[C_ * C_];
__device__ __nv_bfloat16 g_wkb[HD_ * C_];
__device__ __nv_bfloat16 g_wvb[HD_ * C_];
__device__ __nv_bfloat16 g_wob[C_ * C_];
__device__ uint8_t g_q8[(size_t)B_ * N_ * C_];          // Q e4m3, [b][n][c], x (hd^-.5*log2e*SQ)
__device__ uint8_t g_k8[B_ * M_ * HD_];                 // K e4m3, [b][m][d], x SK
__device__ uint8_t g_v8[B_ * HD_ * M_];                 // V e4m3, [b][d][m-permuted], x SV
__device__ __nv_bfloat16 g_ao [(size_t)B_ * N_ * C_];   // attn out, [b][n][c]

// ===================== stats =====================
__global__ void reduce1(const float* __restrict__ x) {
    int b = blockIdx.y, chunk = blockIdx.x, t = threadIdx.x;
    const float4* p = (const float4*)(x + (size_t)b * C_ * N_ + (size_t)chunk * 16384);
    float s = 0.f, sq = 0.f;
#pragma unroll
    for (int i = 0; i < 16; i++) {
        float4 v = p[t + 256 * i];
        s  += v.x + v.y + v.z + v.w;
        sq += v.x * v.x + v.y * v.y + v.z * v.z + v.w * v.w;
    }
    __shared__ float ss[256], sq2[256];
    ss[t] = s; sq2[t] = sq;
    __syncthreads();
    for (int o = 128; o > 0; o >>= 1) {
        if (t < o) { ss[t] += ss[t + o]; sq2[t] += sq2[t + o]; }
        __syncthreads();
    }
    if (t == 0) {
        g_part[(b * 64 + chunk) * 2 + 0] = ss[0];
        g_part[(b * 64 + chunk) * 2 + 1] = sq2[0];
    }
}
__global__ void reduce2(const float* __restrict__ gn_w, const float* __restrict__ gn_b) {
    int b = blockIdx.x, t = threadIdx.x;
    __shared__ float ss[64], sq2[64];
    if (t < 64) { ss[t] = g_part[(b * 64 + t) * 2]; sq2[t] = g_part[(b * 64 + t) * 2 + 1]; }
    __syncthreads();
    for (int o = 32; o > 0; o >>= 1) {
        if (t < o) { ss[t] += ss[t + o]; sq2[t] += sq2[t + o]; }
        __syncthreads();
    }
    __shared__ float sh_mu, sh_inv;
    if (t == 0) {
        const float invN = 1.0f / (float)(C_ * N_);
        float mu  = ss[0] * invN;
        float var = sq2[0] * invN - mu * mu;
        sh_mu = mu; sh_inv = rsqrtf(var + EPSV);
    }
    __syncthreads();
    float sc = sh_inv * gn_w[t];
    g_s[b * C_ + t] = sc;
    g_t[b * C_ + t] = gn_b[t] - sh_mu * sc;
}

// ===================== prep: normalize + transpose to bf16 =====================
__global__ void prep_xt(const float* __restrict__ x) {
    __shared__ float sm[32][33];
    int b = blockIdx.z, c0 = blockIdx.y * 32, n0 = blockIdx.x * 32;
    int tx = threadIdx.x, ty = threadIdx.y;
#pragma unroll
    for (int k = 0; k < 4; k++) {
        int c = c0 + ty + 8 * k;
        float v = x[((size_t)(b * C_ + c)) * N_ + n0 + tx];
        sm[ty + 8 * k][tx] = fmaf(v, g_s[b * C_ + c], g_t[b * C_ + c]);
    }
    __syncthreads();
#pragma unroll
    for (int k = 0; k < 4; k++) {
        int n = n0 + ty + 8 * k;
        g_xt[((size_t)(b * N_ + n)) * C_ + c0 + tx] = __float2bfloat16(sm[tx][ty + 8 * k]);
    }
}
// 2x2 avgpool reading g_xt (bf16), writes g_xds [b][m][c]
__global__ void pool_xt() {
    int t = threadIdx.x;
    int idx = blockIdx.x * 4 + (t >> 6);        // global m-row index: b*1024 + m
    int b = idx >> 10, m = idx & 1023;
    int c4 = (t & 63) * 4;
    int nb = (m >> 5) * 128 + (m & 31) * 2;
    const __nv_bfloat16* base = g_xt + ((size_t)b * N_) * C_ + c4;
    float acc[4] = {0.f, 0.f, 0.f, 0.f};
    int offs[4] = {0, 1, 64, 65};
#pragma unroll
    for (int r = 0; r < 4; r++) {
        uint2 v = *(const uint2*)(base + (size_t)(nb + offs[r]) * C_);
        __nv_bfloat162 p0 = *(__nv_bfloat162*)&v.x;
        __nv_bfloat162 p1 = *(__nv_bfloat162*)&v.y;
        acc[0] += __bfloat162float(p0.x); acc[1] += __bfloat162float(p0.y);
        acc[2] += __bfloat162float(p1.x); acc[3] += __bfloat162float(p1.y);
    }
    uint2 o;
    o.x = pack_bf16x2(acc[0] * 0.25f, acc[1] * 0.25f);
    o.y = pack_bf16x2(acc[2] * 0.25f, acc[3] * 0.25f);
    *(uint2*)(g_xds + ((size_t)b * M_ + m) * C_ + c4) = o;
}
// all weight conversions in one launch
__global__ void cvt_all(const float* __restrict__ wq, const float* __restrict__ wk,
                        const float* __restrict__ wv, const float* __restrict__ wo) {
    const float QS = 0.125f * 1.4426950408889634f * SQ_;
    int i = blockIdx.x * 256 + threadIdx.x;
    if (i < 65536)       g_wqb[i]          = __float2bfloat16(wq[i] * QS);
    else if (i < 81920)  g_wkb[i - 65536]  = __float2bfloat16(wk[i - 65536] * SK_);
    else if (i < 98304)  g_wvb[i - 81920]  = __float2bfloat16(wv[i - 81920] * SV_);
    else if (i < 163840) g_wob[i - 98304]  = __float2bfloat16(wo[i - 98304]);
}

// ===================== projection GEMM: D[128,64-tile] = A[rows,256] @ W[N,256]^T =====
// mode 0: e4m3 out[row][N]; mode 1: e4m3 V transposed+permuted [d][M]; mode 2: fp32 residual
__global__ void __launch_bounds__(256) proj_mma(
    const __nv_bfloat16* __restrict__ A, const __nv_bfloat16* __restrict__ Bw,
    int rows, int N, int mode,
    uint8_t* __restrict__ out8, float* __restrict__ outf,
    const float* __restrict__ xres, const float* __restrict__ gamma)
{
    __shared__ __align__(16) char smraw[33792];
    __nv_bfloat16* As = (__nv_bfloat16*)smraw;             // [128][40]
    __nv_bfloat16* Bs = (__nv_bfloat16*)(smraw + 10240);   // [64][40]
    float* Cs = (float*)smraw;                              // [64][132] epilogue staging

    int t = threadIdx.x, lane = t & 31, wid = t >> 5;
    int wm = wid >> 1, wn = wid & 1;
    int b = blockIdx.z, row0 = blockIdx.x * 128, n0 = blockIdx.y * 64;
    int g = lane >> 2, qt = lane & 3;

    float acc[2][4][4];
#pragma unroll
    for (int mi = 0; mi < 2; mi++)
#pragma unroll
        for (int ni = 0; ni < 4; ni++)
#pragma unroll
            for (int e = 0; e < 4; e++) acc[mi][ni][e] = 0.f;

    const __nv_bfloat16* Ag = A + ((size_t)b * rows + row0) * 256;

    for (int k0 = 0; k0 < 256; k0 += 32) {
#pragma unroll
        for (int i = 0; i < 2; i++) {
            int idx = t + 256 * i;
            int r = idx >> 2, kc = (idx & 3) * 8;
            *(uint4*)(As + r * 40 + kc) = *(const uint4*)(Ag + (size_t)r * 256 + k0 + kc);
        }
        {
            int r = t >> 2, kc = (t & 3) * 8;
            *(uint4*)(Bs + r * 40 + kc) = *(const uint4*)(Bw + (size_t)(n0 + r) * 256 + k0 + kc);
        }
        __syncthreads();
#pragma unroll
        for (int k16 = 0; k16 < 32; k16 += 16) {
            uint32_t af[2][4];
#pragma unroll
            for (int mi = 0; mi < 2; mi++) {
                uint32_t addr = smem_u32(As + (wm * 32 + mi * 16 + (lane & 15)) * 40
                                         + k16 + (lane >> 4) * 8);
                ldmx4(af[mi], addr);
            }
#pragma unroll
            for (int np = 0; np < 2; np++) {
                uint32_t bfm[4];
                uint32_t addr = smem_u32(Bs + (wn * 32 + np * 16 + (lane & 7) + ((lane >> 4) & 1) * 8) * 40
                                         + k16 + ((lane >> 3) & 1) * 8);
                ldmx4(bfm, addr);
                mma16816(acc[0][np * 2 + 0], af[0], bfm[0], bfm[1]);
                mma16816(acc[0][np * 2 + 1], af[0], bfm[2], bfm[3]);
                mma16816(acc[1][np * 2 + 0], af[1], bfm[0], bfm[1]);
                mma16816(acc[1][np * 2 + 1], af[1], bfm[2], bfm[3]);
            }
        }
        __syncthreads();
    }

    if (mode == 0) {
#pragma unroll
        for (int mi = 0; mi < 2; mi++)
#pragma unroll
            for (int ni = 0; ni < 4; ni++) {
                int r = row0 + wm * 32 + mi * 16 + g;
                int col = n0 + wn * 32 + ni * 8 + 2 * qt;
                *(uint16_t*)(out8 + ((size_t)b * rows + r) * N + col) =
                    pack_e4m3x2(acc[mi][ni][0], acc[mi][ni][1]);
                *(uint16_t*)(out8 + ((size_t)b * rows + r + 8) * N + col) =
                    pack_e4m3x2(acc[mi][ni][2], acc[mi][ni][3]);
            }
    } else if (mode == 1) {
#pragma unroll
        for (int mi = 0; mi < 2; mi++)
#pragma unroll
            for (int ni = 0; ni < 4; ni++) {
                int r = row0 + wm * 32 + mi * 16 + g;
                int col = n0 + wn * 32 + ni * 8 + 2 * qt;
                int p0 = perm_v(r), p1 = perm_v(r + 8);
                uint16_t lo = pack_e4m3x2(acc[mi][ni][0], acc[mi][ni][1]);
                uint16_t hi = pack_e4m3x2(acc[mi][ni][2], acc[mi][ni][3]);
                out8[((size_t)b * HD_ + col)     * M_ + p0] = (uint8_t)lo;
                out8[((size_t)b * HD_ + col + 1) * M_ + p0] = (uint8_t)(lo >> 8);
                out8[((size_t)b * HD_ + col)     * M_ + p1] = (uint8_t)hi;
                out8[((size_t)b * HD_ + col + 1) * M_ + p1] = (uint8_t)(hi >> 8);
            }
    } else {
#pragma unroll
        for (int mi = 0; mi < 2; mi++)
#pragma unroll
            for (int ni = 0; ni < 4; ni++) {
                int rL = wm * 32 + mi * 16 + g;
                int cL = wn * 32 + ni * 8 + 2 * qt;
                Cs[cL * 132 + rL]           = acc[mi][ni][0];
                Cs[(cL + 1) * 132 + rL]     = acc[mi][ni][1];
                Cs[cL * 132 + rL + 8]       = acc[mi][ni][2];
                Cs[(cL + 1) * 132 + rL + 8] = acc[mi][ni][3];
            }
        __syncthreads();
#pragma unroll
        for (int i = 0; i < 8; i++) {
            int idx = t + 256 * i;
            int col = idx >> 5, r4 = (idx & 31) * 4;
            float4 v = *(float4*)&Cs[col * 132 + r4];
            size_t off = ((size_t)b * C_ + n0 + col) * (size_t)N_ + row0 + r4;
            float gch = gamma[n0 + col];
            float4 xr = *(const float4*)&xres[off];
            v.x = fmaf(gch, v.x, xr.x);
            v.y = fmaf(gch, v.y, xr.y);
            v.z = fmaf(gch, v.z, xr.z);
            v.w = fmaf(gch, v.w, xr.w);
            *(float4*)&outf[off] = v;
        }
    }
}

// ===================== attention: 128 q/CTA, 8 warps, fp8 e4m3 MMA =====================
__global__ void __launch_bounds__(256) attn_mma() {
    __shared__ __align__(16) uint8_t Ks[64 * 64];   // [m][d] fp8, 16B-chunk XOR swizzle
    __shared__ __align__(16) uint8_t Vs[64 * 64];   // [d][m-perm] fp8, same swizzle

    int t = threadIdx.x, lane = t & 31, w = t >> 5;
    int g = lane >> 2, qt = lane & 3;
    int bh = blockIdx.y, b = bh >> 2, h = bh & 3;
    int n0 = blockIdx.x * 128;

    // Q A-fragments (fp8, k32 x 2 chunks covering d=64) from global
    uint32_t qf[2][4];
    const uint8_t* Qg = g_q8 + ((size_t)b * N_ + n0 + w * 16) * C_ + h * HD_;
#pragma unroll
    for (int ch = 0; ch < 2; ch++) {
        qf[ch][0] = *(const uint32_t*)(Qg + (size_t)g * C_       + ch * 32 + 4 * qt);
        qf[ch][1] = *(const uint32_t*)(Qg + (size_t)(g + 8) * C_ + ch * 32 + 4 * qt);
        qf[ch][2] = *(const uint32_t*)(Qg + (size_t)g * C_       + ch * 32 + 16 + 4 * qt);
        qf[ch][3] = *(const uint32_t*)(Qg + (size_t)(g + 8) * C_ + ch * 32 + 16 + 4 * qt);
    }

    float oacc[8][4];
#pragma unroll
    for (int ud = 0; ud < 8; ud++)
#pragma unroll
        for (int e = 0; e < 4; e++) oacc[ud][e] = 0.f;
    float lsum0 = 0.f, lsum1 = 0.f;

    const uint8_t* Kg = g_k8 + (size_t)b * M_ * HD_;
    const uint8_t* Vg = g_v8 + (size_t)b * HD_ * M_;
    const float SINV = 1.0f / (SQ_ * SK_);

    int frow = t >> 2, fc = t & 3, fsw = (frow >> 1) & 3;
    uint32_t fdst = frow * 64 + ((fc ^ fsw) << 4);

    for (int m0 = 0; m0 < M_; m0 += 64) {
        // fill K/V tiles (coalesced uint4, swizzled chunk placement)
        *(uint4*)(Ks + fdst) = *(const uint4*)(Kg + (size_t)(m0 + frow) * 64 + fc * 16);
        *(uint4*)(Vs + fdst) = *(const uint4*)(Vg + (size_t)frow * M_ + m0 + fc * 16);
        __syncthreads();

        // S = Q K^T (log2 units after SINV)
        float sacc[8][4];
#pragma unroll
        for (int u = 0; u < 8; u++)
#pragma unroll
            for (int e = 0; e < 4; e++) sacc[u][e] = 0.f;
#pragma unroll
        for (int ch = 0; ch < 2; ch++) {
#pragma unroll
            for (int u = 0; u < 8; u++) {
                int r = 8 * u + g, sw = (r >> 1) & 3;
                uint32_t b0 = *(const uint32_t*)(Ks + r * 64 + (((2 * ch) ^ sw) << 4) + 4 * qt);
                uint32_t b1 = *(const uint32_t*)(Ks + r * 64 + (((2 * ch + 1) ^ sw) << 4) + 4 * qt);
                mma16832_e4m3(sacc[u], qf[ch], b0, b1);
            }
        }

        // exp2 + pack directly into fp8 PV A-fragments (V is m-permuted to match)
        uint32_t pa[2][4];
#pragma unroll
        for (int ch = 0; ch < 2; ch++) {
#pragma unroll
            for (int pr = 0; pr < 2; pr++) {
                int u0 = ch * 4 + pr * 2, u1 = u0 + 1;
                float a0 = ex2f(sacc[u0][0] * SINV), a1 = ex2f(sacc[u0][1] * SINV);
                float a2 = ex2f(sacc[u0][2] * SINV), a3 = ex2f(sacc[u0][3] * SINV);
                float b0 = ex2f(sacc[u1][0] * SINV), b1 = ex2f(sacc[u1][1] * SINV);
                float b2 = ex2f(sacc[u1][2] * SINV), b3 = ex2f(sacc[u1][3] * SINV);
                lsum0 += a0 + a1 + b0 + b1;
                lsum1 += a2 + a3 + b2 + b3;
                pa[ch][pr * 2 + 0] = pack_e4m3x4(a0, a1, b0, b1);   // row g
                pa[ch][pr * 2 + 1] = pack_e4m3x4(a2, a3, b2, b3);   // row g+8
            }
            // reorder: built [a0,a1,a2,a3] as [lo g, lo g+8, hi g, hi g+8]
        }
        // fix ordering: pa[ch] currently = {a0(row g,k-lo), a1(row g+8,k-lo), a2(row g,k-hi), a3(row g+8,k-hi)} — correct per PTX A-frag

        // O += P V
#pragma unroll
        for (int ch = 0; ch < 2; ch++) {
#pragma unroll
            for (int ud = 0; ud < 8; ud++) {
                int r = 8 * ud + g, sw = (r >> 1) & 3;
                uint32_t vb0 = *(const uint32_t*)(Vs + r * 64 + (((2 * ch) ^ sw) << 4) + 4 * qt);
                uint32_t vb1 = *(const uint32_t*)(Vs + r * 64 + (((2 * ch + 1) ^ sw) << 4) + 4 * qt);
                mma16832_e4m3(oacc[ud], pa[ch], vb0, vb1);
            }
        }
        __syncthreads();
    }

    // row sums complete within a quad
#pragma unroll
    for (int o = 1; o <= 2; o <<= 1) {
        lsum0 += __shfl_xor_sync(0xffffffffu, lsum0, o);
        lsum1 += __shfl_xor_sync(0xffffffffu, lsum1, o);
    }
    float inv0 = 1.0f / (SV_ * lsum0), inv1 = 1.0f / (SV_ * lsum1);

    __nv_bfloat16* Og = g_ao + ((size_t)b * N_ + n0 + w * 16) * C_ + h * HD_;
#pragma unroll
    for (int ud = 0; ud < 8; ud++) {
        int col = ud * 8 + 2 * qt;
        *(uint32_t*)(Og + (size_t)g * C_ + col) =
            pack_bf16x2(oacc[ud][0] * inv0, oacc[ud][1] * inv0);
        *(uint32_t*)(Og + (size_t)(g + 8) * C_ + col) =
            pack_bf16x2(oacc[ud][2] * inv1, oacc[ud][3] * inv1);
    }
}

// ===================== launch =====================
extern "C" void kernel_launch(void* const* d_in, const int* in_sizes, int n_in,
                              void* d_out, int out_size) {
    const float* x    = (const float*)d_in[0];
    const float* gn_w = (const float*)d_in[1];
    const float* gn_b = (const float*)d_in[2];
    const float* wq   = (const float*)d_in[3];
    const float* wk   = (const float*)d_in[4];
    const float* wv   = (const float*)d_in[5];
    const float* wo   = (const float*)d_in[6];
    const float* gamma= (const float*)d_in[7];
    float* out = (float*)d_out;

    __nv_bfloat16 *pxt, *pxds, *pwq, *pwk, *pwv, *pwo, *pao;
    uint8_t *pq8, *pk8, *pv8;
    cudaGetSymbolAddress((void**)&pxt,  g_xt);
    cudaGetSymbolAddress((void**)&pxds, g_xds);
    cudaGetSymbolAddress((void**)&pwq,  g_wqb);
    cudaGetSymbolAddress((void**)&pwk,  g_wkb);
    cudaGetSymbolAddress((void**)&pwv,  g_wvb);
    cudaGetSymbolAddress((void**)&pwo,  g_wob);
    cudaGetSymbolAddress((void**)&pq8,  g_q8);
    cudaGetSymbolAddress((void**)&pk8,  g_k8);
    cudaGetSymbolAddress((void**)&pv8,  g_v8);
    cudaGetSymbolAddress((void**)&pao,  g_ao);

    reduce1<<<dim3(64, 8), 256>>>(x);
    reduce2<<<8, 256>>>(gn_w, gn_b);
    cvt_all<<<640, 256>>>(wq, wk, wv, wo);

    prep_xt<<<dim3(128, 8, 8), dim3(32, 8)>>>(x);
    pool_xt<<<2048, 256>>>();

    // Q = xt @ wq^T -> fp8 [b][n][256]
    proj_mma<<<dim3(32, 4, 8), 256>>>(pxt, pwq, N_, 256, 0, pq8, nullptr, nullptr, nullptr);
    // K = xds @ wk^T -> fp8 [b][m][64]
    proj_mma<<<dim3(8, 1, 8), 256>>>(pxds, pwk, M_, 64, 0, pk8, nullptr, nullptr, nullptr);
    // V = xds @ wv^T -> fp8 transposed+permuted [b][d][1024]
    proj_mma<<<dim3(8, 1, 8), 256>>>(pxds, pwv, M_, 64, 1, pv8, nullptr, nullptr, nullptr);

    attn_mma<<<dim3(32, 32), 256>>>();

    // out = x + gamma * (ao @ wo^T), channel-major fp32
    proj_mma<<<dim3(32, 4, 8), 256>>>(pao, pwo, N_, 256, 2, nullptr, out, x, gamma);
}

// round 8
// speedup vs baseline: 1.1269x; 1.1269x over previous
#include <cuda_runtime.h>
#include <cuda_bf16.h>
#include <cstdint>

#define B_   8
#define C_   256
#define N_   4096
#define M_   1024
#define HD_  64
#define EPSV 1e-5f

// ===================== helpers =====================
__device__ __forceinline__ uint32_t smem_u32(const void* p) {
    uint32_t a;
    asm("{ .reg .u64 tmp; cvta.to.shared.u64 tmp, %1; cvt.u32.u64 %0, tmp; }" : "=r"(a) : "l"(p));
    return a;
}
__device__ __forceinline__ void ldmx4(uint32_t r[4], uint32_t addr) {
    asm volatile("ldmatrix.sync.aligned.m8n8.x4.shared.b16 {%0,%1,%2,%3}, [%4];"
                 : "=r"(r[0]), "=r"(r[1]), "=r"(r[2]), "=r"(r[3]) : "r"(addr));
}
__device__ __forceinline__ void mma16816(float c[4], const uint32_t a[4], uint32_t b0, uint32_t b1) {
    asm volatile("mma.sync.aligned.m16n8k16.row.col.f32.bf16.bf16.f32 "
                 "{%0,%1,%2,%3}, {%4,%5,%6,%7}, {%8,%9}, {%0,%1,%2,%3};"
                 : "+f"(c[0]), "+f"(c[1]), "+f"(c[2]), "+f"(c[3])
                 : "r"(a[0]), "r"(a[1]), "r"(a[2]), "r"(a[3]), "r"(b0), "r"(b1));
}
__device__ __forceinline__ float ex2f(float x) {
    float r; asm("ex2.approx.ftz.f32 %0, %1;" : "=f"(r) : "f"(x)); return r;
}
__device__ __forceinline__ uint32_t pack_bf16x2(float lo, float hi) {
    uint32_t r;
    asm("cvt.rn.satfinite.bf16x2.f32 %0, %1, %2;" : "=r"(r) : "f"(hi), "f"(lo));
    return r;
}

// ===================== device scratch =====================
__device__ float g_part[B_ * 64 * 2];
__device__ float g_s[B_ * C_];
__device__ float g_t[B_ * C_];
__device__ __nv_bfloat16 g_xt [(size_t)B_ * N_ * C_];   // normalized, [b][n][c]
__device__ __nv_bfloat16 g_xds[(size_t)B_ * M_ * C_];   // pooled+norm, [b][m][c]
__device__ __nv_bfloat16 g_wqb[C_ * C_];
__device__ __nv_bfloat16 g_wkb[HD_ * C_];
__device__ __nv_bfloat16 g_wvb[HD_ * C_];
__device__ __nv_bfloat16 g_wob[C_ * C_];
__device__ __nv_bfloat16 g_qt [(size_t)B_ * N_ * C_];   // Q, [b][n][c]  (pre-scaled by hd^-.5*log2e)
__device__ __nv_bfloat16 g_kt [B_ * M_ * HD_];          // K, [b][m][d]
__device__ __nv_bfloat16 g_vt [B_ * HD_ * M_];          // V, [b][d][m]
__device__ __nv_bfloat16 g_ao [(size_t)B_ * N_ * C_];   // attn out, [b][n][c]

// ===================== stats =====================
__global__ void reduce1(const float* __restrict__ x) {
    int b = blockIdx.y, chunk = blockIdx.x, t = threadIdx.x;
    const float4* p = (const float4*)(x + (size_t)b * C_ * N_ + (size_t)chunk * 16384);
    float s = 0.f, sq = 0.f;
#pragma unroll
    for (int i = 0; i < 16; i++) {
        float4 v = p[t + 256 * i];
        s  += v.x + v.y + v.z + v.w;
        sq += v.x * v.x + v.y * v.y + v.z * v.z + v.w * v.w;
    }
    __shared__ float ss[256], sq2[256];
    ss[t] = s; sq2[t] = sq;
    __syncthreads();
    for (int o = 128; o > 0; o >>= 1) {
        if (t < o) { ss[t] += ss[t + o]; sq2[t] += sq2[t + o]; }
        __syncthreads();
    }
    if (t == 0) {
        g_part[(b * 64 + chunk) * 2 + 0] = ss[0];
        g_part[(b * 64 + chunk) * 2 + 1] = sq2[0];
    }
}
__global__ void reduce2(const float* __restrict__ gn_w, const float* __restrict__ gn_b) {
    int b = blockIdx.x, t = threadIdx.x;
    __shared__ float ss[64], sq2[64];
    if (t < 64) { ss[t] = g_part[(b * 64 + t) * 2]; sq2[t] = g_part[(b * 64 + t) * 2 + 1]; }
    __syncthreads();
    for (int o = 32; o > 0; o >>= 1) {
        if (t < o) { ss[t] += ss[t + o]; sq2[t] += sq2[t + o]; }
        __syncthreads();
    }
    __shared__ float sh_mu, sh_inv;
    if (t == 0) {
        const float invN = 1.0f / (float)(C_ * N_);
        float mu  = ss[0] * invN;
        float var = sq2[0] * invN - mu * mu;
        sh_mu = mu; sh_inv = rsqrtf(var + EPSV);
    }
    __syncthreads();
    float sc = sh_inv * gn_w[t];
    g_s[b * C_ + t] = sc;
    g_t[b * C_ + t] = gn_b[t] - sh_mu * sc;
}

// ===================== prep: normalize + transpose to bf16 (float4 loads) =====
__global__ void prep_xt(const float* __restrict__ x) {
    __shared__ float sm[64 * 65];
    int b = blockIdx.z, c0 = blockIdx.y * 64, n0 = blockIdx.x * 64;
    int t = threadIdx.x;
#pragma unroll
    for (int i = 0; i < 4; i++) {
        int idx = t + 256 * i;
        int c = idx >> 4, ng = (idx & 15) * 4;
        int bc = b * C_ + c0 + c;
        float4 v = *(const float4*)&x[(size_t)bc * N_ + n0 + ng];
        float s = g_s[bc], tt = g_t[bc];
        sm[(ng + 0) * 65 + c] = fmaf(v.x, s, tt);
        sm[(ng + 1) * 65 + c] = fmaf(v.y, s, tt);
        sm[(ng + 2) * 65 + c] = fmaf(v.z, s, tt);
        sm[(ng + 3) * 65 + c] = fmaf(v.w, s, tt);
    }
    __syncthreads();
#pragma unroll
    for (int i = 0; i < 4; i++) {
        int idx = t + 256 * i;
        int cg = idx & 15, n = idx >> 4;
        const float* r = &sm[n * 65 + cg * 4];
        uint2 o;
        o.x = pack_bf16x2(r[0], r[1]);
        o.y = pack_bf16x2(r[2], r[3]);
        *(uint2*)(g_xt + ((size_t)(b * N_ + n0 + n)) * C_ + c0 + cg * 4) = o;
    }
}
// 2x2 avgpool reading g_xt (bf16), writes g_xds [b][m][c]
__global__ void pool_xt() {
    int t = threadIdx.x;
    int idx = blockIdx.x * 4 + (t >> 6);
    int b = idx >> 10, m = idx & 1023;
    int c4 = (t & 63) * 4;
    int nb = (m >> 5) * 128 + (m & 31) * 2;
    const __nv_bfloat16* base = g_xt + ((size_t)b * N_) * C_ + c4;
    float acc[4] = {0.f, 0.f, 0.f, 0.f};
    int offs[4] = {0, 1, 64, 65};
#pragma unroll
    for (int r = 0; r < 4; r++) {
        uint2 v = *(const uint2*)(base + (size_t)(nb + offs[r]) * C_);
        __nv_bfloat162 p0 = *(__nv_bfloat162*)&v.x;
        __nv_bfloat162 p1 = *(__nv_bfloat162*)&v.y;
        acc[0] += __bfloat162float(p0.x); acc[1] += __bfloat162float(p0.y);
        acc[2] += __bfloat162float(p1.x); acc[3] += __bfloat162float(p1.y);
    }
    uint2 o;
    o.x = pack_bf16x2(acc[0] * 0.25f, acc[1] * 0.25f);
    o.y = pack_bf16x2(acc[2] * 0.25f, acc[3] * 0.25f);
    *(uint2*)(g_xds + ((size_t)b * M_ + m) * C_ + c4) = o;
}
// all weight conversions in one launch (wq folds hd^-0.5 * log2e)
__global__ void cvt_all(const float* __restrict__ wq, const float* __restrict__ wk,
                        const float* __restrict__ wv, const float* __restrict__ wo) {
    const float QS = 0.125f * 1.4426950408889634f;
    int i = blockIdx.x * 256 + threadIdx.x;
    if (i < 65536)       g_wqb[i]          = __float2bfloat16(wq[i] * QS);
    else if (i < 81920)  g_wkb[i - 65536]  = __float2bfloat16(wk[i - 65536]);
    else if (i < 98304)  g_wvb[i - 81920]  = __float2bfloat16(wv[i - 81920]);
    else if (i < 163840) g_wob[i - 98304]  = __float2bfloat16(wo[i - 98304]);
}

// ===================== projection GEMM, templated n-tile =====================
// CTA: 128 rows x NT cols, K=256, 8 warps (4 m-quarters x 2 n-halves).
// mode 0: bf16 out[row][N]; mode 1: bf16 V transposed [d][M]; mode 2: fp32 residual out
template<int NT>
__global__ void __launch_bounds__(256) proj_mma(
    const __nv_bfloat16* __restrict__ A, const __nv_bfloat16* __restrict__ Bw,
    int rows, int N, int mode,
    __nv_bfloat16* __restrict__ outb, float* __restrict__ outf,
    const float* __restrict__ xres, const float* __restrict__ gamma)
{
    extern __shared__ char dsm[];
    __nv_bfloat16* As = (__nv_bfloat16*)dsm;              // [128][40]
    __nv_bfloat16* Bs = (__nv_bfloat16*)(dsm + 10240);    // [NT][40]
    float* Cs = (float*)dsm;                               // [NT][132] epilogue staging

    constexpr int NFR = NT / 16;        // n8-frags per warp
    int t = threadIdx.x, lane = t & 31, wid = t >> 5;
    int wm = wid & 3, wn = wid >> 2;
    int b = blockIdx.z, row0 = blockIdx.x * 128, n0 = blockIdx.y * NT;
    int g = lane >> 2, qt = lane & 3;

    float acc[2][NFR][4];
#pragma unroll
    for (int mi = 0; mi < 2; mi++)
#pragma unroll
        for (int ni = 0; ni < NFR; ni++)
#pragma unroll
            for (int e = 0; e < 4; e++) acc[mi][ni][e] = 0.f;

    const __nv_bfloat16* Ag = A + ((size_t)b * rows + row0) * 256;

    for (int k0 = 0; k0 < 256; k0 += 32) {
#pragma unroll
        for (int i = 0; i < 2; i++) {
            int idx = t + 256 * i;
            int r = idx >> 2, kc = (idx & 3) * 8;
            *(uint4*)(As + r * 40 + kc) = *(const uint4*)(Ag + (size_t)r * 256 + k0 + kc);
        }
#pragma unroll
        for (int i = 0; i < NT / 64; i++) {
            int idx = t + 256 * i;
            int r = idx >> 2, kc = (idx & 3) * 8;
            *(uint4*)(Bs + r * 40 + kc) = *(const uint4*)(Bw + (size_t)(n0 + r) * 256 + k0 + kc);
        }
        __syncthreads();
#pragma unroll
        for (int k16 = 0; k16 < 32; k16 += 16) {
            uint32_t af[2][4];
#pragma unroll
            for (int mi = 0; mi < 2; mi++) {
                uint32_t addr = smem_u32(As + (wm * 32 + mi * 16 + (lane & 15)) * 40
                                         + k16 + (lane >> 4) * 8);
                ldmx4(af[mi], addr);
            }
#pragma unroll
            for (int np = 0; np < NFR / 2; np++) {
                uint32_t bfm[4];
                uint32_t addr = smem_u32(Bs + (wn * (NT / 2) + np * 16 + (lane & 7) + ((lane >> 4) & 1) * 8) * 40
                                         + k16 + ((lane >> 3) & 1) * 8);
                ldmx4(bfm, addr);
                mma16816(acc[0][np * 2 + 0], af[0], bfm[0], bfm[1]);
                mma16816(acc[0][np * 2 + 1], af[0], bfm[2], bfm[3]);
                mma16816(acc[1][np * 2 + 0], af[1], bfm[0], bfm[1]);
                mma16816(acc[1][np * 2 + 1], af[1], bfm[2], bfm[3]);
            }
        }
        __syncthreads();
    }

    if (mode == 0) {
#pragma unroll
        for (int mi = 0; mi < 2; mi++)
#pragma unroll
            for (int ni = 0; ni < NFR; ni++) {
                int r = row0 + wm * 32 + mi * 16 + g;
                int col = n0 + wn * (NT / 2) + ni * 8 + 2 * qt;
                *(uint32_t*)(outb + ((size_t)b * rows + r) * N + col) =
                    pack_bf16x2(acc[mi][ni][0], acc[mi][ni][1]);
                *(uint32_t*)(outb + ((size_t)b * rows + r + 8) * N + col) =
                    pack_bf16x2(acc[mi][ni][2], acc[mi][ni][3]);
            }
    } else if (mode == 1) {
#pragma unroll
        for (int mi = 0; mi < 2; mi++)
#pragma unroll
            for (int ni = 0; ni < NFR; ni++) {
                int r = row0 + wm * 32 + mi * 16 + g;
                int col = n0 + wn * (NT / 2) + ni * 8 + 2 * qt;
                outb[((size_t)b * HD_ + col)     * M_ + r]     = __float2bfloat16(acc[mi][ni][0]);
                outb[((size_t)b * HD_ + col + 1) * M_ + r]     = __float2bfloat16(acc[mi][ni][1]);
                outb[((size_t)b * HD_ + col)     * M_ + r + 8] = __float2bfloat16(acc[mi][ni][2]);
                outb[((size_t)b * HD_ + col + 1) * M_ + r + 8] = __float2bfloat16(acc[mi][ni][3]);
            }
    } else {
        // stage Cs[col][row] then coalesced channel-major residual store
#pragma unroll
        for (int mi = 0; mi < 2; mi++)
#pragma unroll
            for (int ni = 0; ni < NFR; ni++) {
                int rL = wm * 32 + mi * 16 + g;
                int cL = wn * (NT / 2) + ni * 8 + 2 * qt;
                Cs[cL * 132 + rL]           = acc[mi][ni][0];
                Cs[(cL + 1) * 132 + rL]     = acc[mi][ni][1];
                Cs[cL * 132 + rL + 8]       = acc[mi][ni][2];
                Cs[(cL + 1) * 132 + rL + 8] = acc[mi][ni][3];
            }
        __syncthreads();
#pragma unroll
        for (int i = 0; i < NT / 8; i++) {
            int idx = t + 256 * i;
            int col = idx >> 5, r4 = (idx & 31) * 4;
            float4 v = *(float4*)&Cs[col * 132 + r4];
            size_t off = ((size_t)b * C_ + n0 + col) * (size_t)N_ + row0 + r4;
            float gch = gamma[n0 + col];
            float4 xr = *(const float4*)&xres[off];
            v.x = fmaf(gch, v.x, xr.x);
            v.y = fmaf(gch, v.y, xr.y);
            v.z = fmaf(gch, v.z, xr.z);
            v.w = fmaf(gch, v.w, xr.w);
            *(float4*)&outf[off] = v;
        }
    }
}

// ===================== attention: 128 q/CTA, 8 warps (16 q each), bf16 HMMA ==========
__global__ void __launch_bounds__(256) attn_mma() {
    __shared__ __align__(16) __nv_bfloat16 Ks[64 * 72];   // [m][d] pad 72
    __shared__ __align__(16) __nv_bfloat16 Vs[64 * 72];   // [d][m] pad 72

    int t = threadIdx.x, lane = t & 31, w = t >> 5;
    int g = lane >> 2, qt = lane & 3;
    int bh = blockIdx.y, b = bh >> 2, h = bh & 3;
    int n0 = blockIdx.x * 128;

    uint32_t qf[4][4];
    const __nv_bfloat16* Qg = g_qt + ((size_t)b * N_ + n0 + w * 16) * C_ + h * HD_;
#pragma unroll
    for (int k16 = 0; k16 < 4; k16++) {
        qf[k16][0] = *(const uint32_t*)(Qg + (size_t)g * C_       + k16 * 16 + 2 * qt);
        qf[k16][1] = *(const uint32_t*)(Qg + (size_t)(g + 8) * C_ + k16 * 16 + 2 * qt);
        qf[k16][2] = *(const uint32_t*)(Qg + (size_t)g * C_       + k16 * 16 + 8 + 2 * qt);
        qf[k16][3] = *(const uint32_t*)(Qg + (size_t)(g + 8) * C_ + k16 * 16 + 8 + 2 * qt);
    }

    float oacc[8][4];
#pragma unroll
    for (int ni = 0; ni < 8; ni++)
#pragma unroll
        for (int e = 0; e < 4; e++) oacc[ni][e] = 0.f;
    float lsum0 = 0.f, lsum1 = 0.f;

    const __nv_bfloat16* Kg = g_kt + (size_t)b * M_ * HD_;
    const __nv_bfloat16* Vg = g_vt + (size_t)b * HD_ * M_;

    for (int m0 = 0; m0 < M_; m0 += 64) {
#pragma unroll
        for (int i = 0; i < 2; i++) {
            int idx = t + 256 * i;
            int r = idx >> 3, cc = (idx & 7) * 8;
            *(uint4*)(Ks + r * 72 + cc) = *(const uint4*)(Kg + (size_t)(m0 + r) * HD_ + cc);
            *(uint4*)(Vs + r * 72 + cc) = *(const uint4*)(Vg + (size_t)r * M_ + m0 + cc);
        }
        __syncthreads();

        float sacc[8][4];
#pragma unroll
        for (int ni = 0; ni < 8; ni++)
#pragma unroll
            for (int e = 0; e < 4; e++) sacc[ni][e] = 0.f;
#pragma unroll
        for (int k16 = 0; k16 < 4; k16++) {
#pragma unroll
            for (int np = 0; np < 4; np++) {
                uint32_t bfm[4];
                uint32_t addr = smem_u32(Ks + (np * 16 + (lane & 7) + ((lane >> 4) & 1) * 8) * 72
                                         + k16 * 16 + ((lane >> 3) & 1) * 8);
                ldmx4(bfm, addr);
                mma16816(sacc[np * 2 + 0], qf[k16], bfm[0], bfm[1]);
                mma16816(sacc[np * 2 + 1], qf[k16], bfm[2], bfm[3]);
            }
        }

        uint32_t pa[4][4];
#pragma unroll
        for (int j = 0; j < 4; j++) {
            float e00 = ex2f(sacc[2 * j][0]),     e01 = ex2f(sacc[2 * j][1]);
            float e10 = ex2f(sacc[2 * j][2]),     e11 = ex2f(sacc[2 * j][3]);
            float f00 = ex2f(sacc[2 * j + 1][0]), f01 = ex2f(sacc[2 * j + 1][1]);
            float f10 = ex2f(sacc[2 * j + 1][2]), f11 = ex2f(sacc[2 * j + 1][3]);
            lsum0 += e00 + e01 + f00 + f01;
            lsum1 += e10 + e11 + f10 + f11;
            pa[j][0] = pack_bf16x2(e00, e01);
            pa[j][1] = pack_bf16x2(e10, e11);
            pa[j][2] = pack_bf16x2(f00, f01);
            pa[j][3] = pack_bf16x2(f10, f11);
        }

#pragma unroll
        for (int k16 = 0; k16 < 4; k16++) {
#pragma unroll
            for (int np = 0; np < 4; np++) {
                uint32_t bfm[4];
                uint32_t addr = smem_u32(Vs + (np * 16 + (lane & 7) + ((lane >> 4) & 1) * 8) * 72
                                         + k16 * 16 + ((lane >> 3) & 1) * 8);
                ldmx4(bfm, addr);
                mma16816(oacc[np * 2 + 0], pa[k16], bfm[0], bfm[1]);
                mma16816(oacc[np * 2 + 1], pa[k16], bfm[2], bfm[3]);
            }
        }
        __syncthreads();
    }

#pragma unroll
    for (int o = 1; o <= 2; o <<= 1) {
        lsum0 += __shfl_xor_sync(0xffffffffu, lsum0, o);
        lsum1 += __shfl_xor_sync(0xffffffffu, lsum1, o);
    }
    float inv0 = 1.0f / lsum0, inv1 = 1.0f / lsum1;

    __nv_bfloat16* Og = g_ao + ((size_t)b * N_ + n0 + w * 16) * C_ + h * HD_;
#pragma unroll
    for (int ni = 0; ni < 8; ni++) {
        int col = ni * 8 + 2 * qt;
        *(uint32_t*)(Og + (size_t)g * C_ + col) =
            pack_bf16x2(oacc[ni][0] * inv0, oacc[ni][1] * inv0);
        *(uint32_t*)(Og + (size_t)(g + 8) * C_ + col) =
            pack_bf16x2(oacc[ni][2] * inv1, oacc[ni][3] * inv1);
    }
}

// ===================== launch =====================
extern "C" void kernel_launch(void* const* d_in, const int* in_sizes, int n_in,
                              void* d_out, int out_size) {
    const float* x    = (const float*)d_in[0];
    const float* gn_w = (const float*)d_in[1];
    const float* gn_b = (const float*)d_in[2];
    const float* wq   = (const float*)d_in[3];
    const float* wk   = (const float*)d_in[4];
    const float* wv   = (const float*)d_in[5];
    const float* wo   = (const float*)d_in[6];
    const float* gamma= (const float*)d_in[7];
    float* out = (float*)d_out;

    __nv_bfloat16 *pxt, *pxds, *pwq, *pwk, *pwv, *pwo, *pqt, *pkt, *pvt, *pao;
    cudaGetSymbolAddress((void**)&pxt,  g_xt);
    cudaGetSymbolAddress((void**)&pxds, g_xds);
    cudaGetSymbolAddress((void**)&pwq,  g_wqb);
    cudaGetSymbolAddress((void**)&pwk,  g_wkb);
    cudaGetSymbolAddress((void**)&pwv,  g_wvb);
    cudaGetSymbolAddress((void**)&pwo,  g_wob);
    cudaGetSymbolAddress((void**)&pqt,  g_qt);
    cudaGetSymbolAddress((void**)&pkt,  g_kt);
    cudaGetSymbolAddress((void**)&pvt,  g_vt);
    cudaGetSymbolAddress((void**)&pao,  g_ao);

    // opt-in >48KB dynamic smem for the 128-wide proj (O-proj epilogue staging)
    cudaFuncSetAttribute(proj_mma<128>, cudaFuncAttributeMaxDynamicSharedMemorySize, 67584);

    reduce1<<<dim3(64, 8), 256>>>(x);
    reduce2<<<8, 256>>>(gn_w, gn_b);
    cvt_all<<<640, 256>>>(wq, wk, wv, wo);

    prep_xt<<<dim3(64, 4, 8), 256>>>(x);
    pool_xt<<<2048, 256>>>();

    // Q = xt @ wq^T -> bf16 [b][n][256]
    proj_mma<128><<<dim3(32, 2, 8), 256, 20480>>>(pxt, pwq, N_, 256, 0, pqt, nullptr, nullptr, nullptr);
    // K = xds @ wk^T -> bf16 [b][m][64]
    proj_mma<64><<<dim3(8, 1, 8), 256, 15360>>>(pxds, pwk, M_, 64, 0, pkt, nullptr, nullptr, nullptr);
    // V = xds @ wv^T -> bf16 transposed [b][d][1024]
    proj_mma<64><<<dim3(8, 1, 8), 256, 15360>>>(pxds, pwv, M_, 64, 1, pvt, nullptr, nullptr, nullptr);

    attn_mma<<<dim3(32, 32), 256>>>();

    // out = x + gamma * (ao @ wo^T), channel-major fp32
    proj_mma<128><<<dim3(32, 2, 8), 256, 67584>>>(pao, pwo, N_, 256, 2, nullptr, out, x, gamma);
}